// round 1
// baseline (speedup 1.0000x reference)
#include <cuda_runtime.h>
#include <cuda_bf16.h>

// LengthRegulator: out[b,t,:] = x[b, searchsorted(cumsum(dur[b]), t, 'right'), :]
// (zeros for t >= total duration). Shapes fixed by the problem:
//   x: [16, 512, 512] f32, durations: [16, 512] i32, out: [16, 4096, 512] f32.

static constexpr int B  = 16;
static constexpr int S  = 512;
static constexpr int H  = 512;
static constexpr int T  = 4096;
static constexpr int H4 = H / 4;          // 128 float4 per row
static constexpr long long TOTAL4 = (long long)B * T * H4;  // 8,388,608

// Scratch: per-frame source-token index (S means "invalid / zero frame").
__device__ int g_idx[B * T];

// One block per batch: inclusive scan of durations in shared memory, then
// binary search for each of the T output frames.
__global__ void scan_idx_kernel(const int* __restrict__ durations) {
    __shared__ int cum[S];
    const int b   = blockIdx.x;
    const int tid = threadIdx.x;          // blockDim.x == S == 512

    cum[tid] = durations[b * S + tid];
    __syncthreads();

    // Hillis-Steele inclusive scan (9 rounds for S=512).
    #pragma unroll
    for (int off = 1; off < S; off <<= 1) {
        int add = (tid >= off) ? cum[tid - off] : 0;
        __syncthreads();
        cum[tid] += add;
        __syncthreads();
    }

    const int total = cum[S - 1];

    // Each thread resolves T/S = 8 frames: first j with cum[j] > t
    // (== numpy searchsorted side='right'); t >= total -> S (invalid).
    for (int t = tid; t < T; t += S) {
        int idx;
        if (t >= total) {
            idx = S;
        } else {
            int lo = 0, hi = S - 1;
            while (lo < hi) {
                int mid = (lo + hi) >> 1;
                if (cum[mid] > t) hi = mid; else lo = mid + 1;
            }
            idx = lo;
        }
        g_idx[b * T + t] = idx;
    }
}

// One float4 per thread. All index math is shifts (H4=128, T=4096 are pow2).
__global__ void gather_kernel(const float4* __restrict__ x,
                              float4* __restrict__ out) {
    const int i = blockIdx.x * blockDim.x + threadIdx.x;  // < 2^23, fits int
    const int row = i >> 7;          // / H4
    const int h   = i & (H4 - 1);
    const int b   = row >> 12;       // / T

    const int idx = g_idx[row];      // uniform across 128 consecutive threads
    if (idx < S) {
        out[i] = x[(b * S + idx) * H4 + h];
    } else {
        out[i] = make_float4(0.f, 0.f, 0.f, 0.f);
    }
}

extern "C" void kernel_launch(void* const* d_in, const int* in_sizes, int n_in,
                              void* d_out, int out_size) {
    const float* x   = (const float*)d_in[0];      // [B, S, H] f32
    const int*   dur = (const int*)d_in[1];        // [B, S]   i32
    float*       out = (float*)d_out;              // [B, T, H] f32
    (void)in_sizes; (void)n_in; (void)out_size;

    scan_idx_kernel<<<B, S>>>(dur);

    const int threads = 256;
    const int blocks  = (int)(TOTAL4 / threads);   // 32768
    gather_kernel<<<blocks, threads>>>((const float4*)x, (float4*)out);
}

// round 2
// speedup vs baseline: 1.3591x; 1.3591x over previous
#include <cuda_runtime.h>
#include <cuda_bf16.h>

// LengthRegulator: out[b,t,:] = x[b, searchsorted(cumsum(dur[b]), t, 'right'), :]
// (zeros for t >= total duration). Shapes fixed by the problem:
//   x: [16, 512, 512] f32, durations: [16, 512] i32, out: [16, 4096, 512] f32.

static constexpr int B  = 16;
static constexpr int S  = 512;
static constexpr int H  = 512;
static constexpr int T  = 4096;
static constexpr int H4 = H / 4;          // 128 float4 per row

// Scratch: per-frame source-token index (S means "invalid / zero frame").
__device__ int g_idx[B * T];

// One block per batch: inclusive scan of durations in shared memory, then
// binary search for each of the T output frames.
__global__ void scan_idx_kernel(const int* __restrict__ durations) {
    __shared__ int cum[S];
    const int b   = blockIdx.x;
    const int tid = threadIdx.x;          // blockDim.x == S == 512

    cum[tid] = durations[b * S + tid];
    __syncthreads();

    // Hillis-Steele inclusive scan (9 rounds for S=512).
    #pragma unroll
    for (int off = 1; off < S; off <<= 1) {
        int add = (tid >= off) ? cum[tid - off] : 0;
        __syncthreads();
        cum[tid] += add;
        __syncthreads();
    }

    const int total = cum[S - 1];

    // Each thread resolves T/S = 8 frames: first j with cum[j] > t
    // (== numpy searchsorted side='right'); t >= total -> S (invalid).
    for (int t = tid; t < T; t += S) {
        int idx;
        if (t >= total) {
            idx = S;
        } else {
            int lo = 0, hi = S - 1;
            while (lo < hi) {
                int mid = (lo + hi) >> 1;
                if (cum[mid] > t) hi = mid; else lo = mid + 1;
            }
            idx = lo;
        }
        g_idx[b * T + t] = idx;
    }
}

// One WARP per output row [b,t]; each lane moves 4 float4s (lane, +32, +64, +96)
// so the warp covers the full 512-float row with 4 perfectly-coalesced 512B
// wavefronts and MLP=4 independent LDG.128 per thread.
__global__ void gather_kernel(const float4* __restrict__ x,
                              float4* __restrict__ out) {
    const int warps_per_block = blockDim.x >> 5;
    const int row  = blockIdx.x * warps_per_block + (threadIdx.x >> 5); // [0, B*T)
    const int lane = threadIdx.x & 31;
    const int b    = row >> 12;           // / T

    const int idx = g_idx[row];           // uniform across the warp (1 sector)
    float4* o = out + ((long long)row << 7);

    if (idx < S) {
        const float4* src = x + ((long long)((b << 9) + idx) << 7);
        float4 v0 = src[lane];
        float4 v1 = src[lane + 32];
        float4 v2 = src[lane + 64];
        float4 v3 = src[lane + 96];
        o[lane]      = v0;
        o[lane + 32] = v1;
        o[lane + 64] = v2;
        o[lane + 96] = v3;
    } else {
        const float4 z = make_float4(0.f, 0.f, 0.f, 0.f);
        o[lane]      = z;
        o[lane + 32] = z;
        o[lane + 64] = z;
        o[lane + 96] = z;
    }
}

extern "C" void kernel_launch(void* const* d_in, const int* in_sizes, int n_in,
                              void* d_out, int out_size) {
    const float* x   = (const float*)d_in[0];      // [B, S, H] f32
    const int*   dur = (const int*)d_in[1];        // [B, S]   i32
    float*       out = (float*)d_out;              // [B, T, H] f32
    (void)in_sizes; (void)n_in; (void)out_size;

    scan_idx_kernel<<<B, S>>>(dur);

    const int threads = 256;                       // 8 warps = 8 rows per block
    const int blocks  = (B * T) / (threads / 32);  // 8192
    gather_kernel<<<blocks, threads>>>((const float4*)x, (float4*)out);
}

// round 3
// speedup vs baseline: 1.4476x; 1.0651x over previous
#include <cuda_runtime.h>
#include <cuda_bf16.h>

// LengthRegulator: out[b,t,:] = x[b, searchsorted(cumsum(dur[b]), t, 'right'), :]
// (zeros for t >= total duration). Shapes fixed by the problem:
//   x: [16, 512, 512] f32, durations: [16, 512] i32, out: [16, 4096, 512] f32.

static constexpr int B  = 16;
static constexpr int S  = 512;
static constexpr int H  = 512;
static constexpr int T  = 4096;
static constexpr int H4 = H / 4;          // 128 float4 per row

// Scratch: per-frame source-token index (S means "invalid / zero frame").
__device__ int g_idx[B * T];

// One block per batch. Warp-shuffle inclusive scan of durations (no smem
// ping-pong), then SCATTER: token j owns frames [cum[j-1], cum[j]) and writes
// its own index there; tail frames [total, T) get S. Replaces the 9-round
// dependent-LDS binary search entirely.
__global__ void scan_idx_kernel(const int* __restrict__ durations) {
    __shared__ int warp_sums[16];
    __shared__ int s_total;
    const int b    = blockIdx.x;
    const int tid  = threadIdx.x;         // blockDim.x == S == 512
    const int lane = tid & 31;
    const int wid  = tid >> 5;            // 16 warps

    const int d = durations[b * S + tid];

    // Warp-level inclusive scan (5 shuffle steps).
    int v = d;
    #pragma unroll
    for (int off = 1; off < 32; off <<= 1) {
        int n = __shfl_up_sync(0xffffffffu, v, off);
        if (lane >= off) v += n;
    }
    if (lane == 31) warp_sums[wid] = v;
    __syncthreads();

    // Warp 0 scans the 16 warp totals.
    if (wid == 0 && lane < 16) {
        int w = warp_sums[lane];
        #pragma unroll
        for (int off = 1; off < 16; off <<= 1) {
            int n = __shfl_up_sync(0xffffu, w, off);
            if (lane >= off) w += n;
        }
        warp_sums[lane] = w;
        if (lane == 15) s_total = w;
    }
    __syncthreads();

    const int cum   = v + (wid > 0 ? warp_sums[wid - 1] : 0);  // inclusive
    const int start = cum - d;                                  // exclusive
    const int total = s_total;
    int* __restrict__ gi = g_idx + b * T;

    // Scatter this token's index over its span (<=15 writes, adjacent spans
    // are contiguous so stores coalesce at the cache-line level).
    for (int t = start; t < cum; ++t) gi[t] = tid;

    // Tail fill: frames beyond total get the invalid marker S.
    for (int t = total + tid; t < T; t += S) gi[t] = S;
}

// One WARP per PAIR of consecutive output rows. Each lane moves 4 float4s per
// row (full 2KB row per warp, 4 coalesced 512B wavefronts, MLP up to 8).
// Adjacent frames share a source token ~87% of the time (E[dur]~7.5), so the
// warp-uniform idx1==idx0 check reuses registers and skips the second L2 read.
__global__ void gather_kernel(const float4* __restrict__ x,
                              float4* __restrict__ out) {
    const int w    = blockIdx.x * (blockDim.x >> 5) + (threadIdx.x >> 5);
    const int row0 = w << 1;              // even; row1 = row0+1 (same batch)
    const int lane = threadIdx.x & 31;
    const int b    = row0 >> 12;          // / T

    const int idx0 = g_idx[row0];
    const int idx1 = g_idx[row0 + 1];

    const float4 z = make_float4(0.f, 0.f, 0.f, 0.f);
    float4 a0 = z, a1 = z, a2 = z, a3 = z;
    float4 c0 = z, c1 = z, c2 = z, c3 = z;

    if (idx0 < S) {
        const float4* s = x + ((long long)((b << 9) + idx0) << 7);
        a0 = s[lane];      a1 = s[lane + 32];
        a2 = s[lane + 64]; a3 = s[lane + 96];
    }
    if (idx1 < S) {
        if (idx1 == idx0) {               // warp-uniform fast path (~87%)
            c0 = a0; c1 = a1; c2 = a2; c3 = a3;
        } else {
            const float4* s = x + ((long long)((b << 9) + idx1) << 7);
            c0 = s[lane];      c1 = s[lane + 32];
            c2 = s[lane + 64]; c3 = s[lane + 96];
        }
    }

    float4* o0 = out + ((long long)row0 << 7);
    float4* o1 = o0 + H4;
    o0[lane]      = a0;  o0[lane + 32] = a1;
    o0[lane + 64] = a2;  o0[lane + 96] = a3;
    o1[lane]      = c0;  o1[lane + 32] = c1;
    o1[lane + 64] = c2;  o1[lane + 96] = c3;
}

extern "C" void kernel_launch(void* const* d_in, const int* in_sizes, int n_in,
                              void* d_out, int out_size) {
    const float* x   = (const float*)d_in[0];      // [B, S, H] f32
    const int*   dur = (const int*)d_in[1];        // [B, S]   i32
    float*       out = (float*)d_out;              // [B, T, H] f32
    (void)in_sizes; (void)n_in; (void)out_size;

    scan_idx_kernel<<<B, S>>>(dur);

    const int threads = 256;                        // 8 warps = 16 rows/block
    const int blocks  = (B * T) / ((threads / 32) * 2);  // 4096
    gather_kernel<<<blocks, threads>>>((const float4*)x, (float4*)out);
}